// round 16
// baseline (speedup 1.0000x reference)
#include <cuda_runtime.h>
#include <cuda_bf16.h>
#include <cstdint>

#define N_NODES 50000
#define E_EDGES 800000
#define F_IN    128
#define F_OUT   64

// Static scratch
__device__ float g_support[N_NODES * F_OUT];   // (X@W)*t  12.8 MB
__device__ int   g_count[N_NODES];             // zeroed by kernel1; hist->cursor
__device__ int   g_start[N_NODES + 1];         // CSR offsets (by src)
__device__ int   g_bsum[256];                  // block sums for scan
__device__ int2  g_edges[E_EDGES];             // (dst, val bits) sorted by src

// grid barrier state (count self-resets -> replay-deterministic)
__device__ int g_bar_count;
__device__ int g_bar_gen;

#define FB 444                                 // persistent blocks (148*3)
#define SCAN_B 196                             // ceil(50000/256)

// ===========================================================================
// Kernel 1: GEMM (proven R12/R14) + bias-init of out + zero g_count.
// ===========================================================================
#define GT 256
#define ASTR 272
#define SM_BHI 0
#define SM_BLO (SM_BHI + 64 * ASTR)
#define SM_TOTAL (SM_BLO + 64 * ASTR)          // 34816

__device__ __forceinline__ uint32_t smem_u32(const void* p) {
    uint32_t a;
    asm("{ .reg .u64 tmp; cvta.to.shared.u64 tmp, %1; cvt.u32.u64 %0, tmp; }"
        : "=r"(a) : "l"(p));
    return a;
}

__device__ __forceinline__ void ldmatrix_x4(uint32_t* r, uint32_t addr) {
    asm volatile("ldmatrix.sync.aligned.m8n8.x4.shared.b16 {%0,%1,%2,%3}, [%4];"
                 : "=r"(r[0]), "=r"(r[1]), "=r"(r[2]), "=r"(r[3]) : "r"(addr));
}

__device__ __forceinline__ void mma_bf16(float* d, const uint32_t* a,
                                         const uint32_t* b) {
    asm volatile(
        "mma.sync.aligned.m16n8k16.row.col.f32.bf16.bf16.f32 "
        "{%0,%1,%2,%3}, {%4,%5,%6,%7}, {%8,%9}, {%0,%1,%2,%3};"
        : "+f"(d[0]), "+f"(d[1]), "+f"(d[2]), "+f"(d[3])
        : "r"(a[0]), "r"(a[1]), "r"(a[2]), "r"(a[3]), "r"(b[0]), "r"(b[1]));
}

__device__ __forceinline__ uint32_t pack_hi(float2 v) {
    __nv_bfloat162 h = __floats2bfloat162_rn(v.x, v.y);
    return *(uint32_t*)&h;
}
__device__ __forceinline__ uint32_t pack_lo(float2 v) {
    __nv_bfloat162 h = __floats2bfloat162_rn(v.x, v.y);
    float rx = v.x - __bfloat162float(__low2bfloat16(h));
    float ry = v.y - __bfloat162float(__high2bfloat16(h));
    __nv_bfloat162 l = __floats2bfloat162_rn(rx, ry);
    return *(uint32_t*)&l;
}

__global__ void __launch_bounds__(GT, 3)
gemm_tc_kernel(const float* __restrict__ x,
               const float* __restrict__ t,
               const float* __restrict__ weight,
               const float* __restrict__ bias,
               float* __restrict__ out)
{
    extern __shared__ char smem[];
    const uint32_t sb = smem_u32(smem);
    const int tid  = threadIdx.x;
    const int wid  = tid >> 5;
    const int lane = tid & 31;
    const int row0 = blockIdx.x * 128;

    for (int i = tid; i < F_IN * F_OUT; i += GT) {
        int f = i & 63;
        int k = i >> 6;
        float v = __ldg(&weight[i]);
        __nv_bfloat16 h = __float2bfloat16(v);
        __nv_bfloat16 l = __float2bfloat16(v - __bfloat162float(h));
        *(__nv_bfloat16*)(smem + SM_BHI + f * ASTR + k * 2) = h;
        *(__nv_bfloat16*)(smem + SM_BLO + f * ASTR + k * 2) = l;
    }
    __syncthreads();

    const int g   = lane >> 2;
    const int tig = lane & 3;
    const int r0g = row0 + wid * 16 + g;
    const int r1g = r0g + 8;
    const bool v0 = r0g < N_NODES;
    const bool v1 = r1g < N_NODES;
    const float2* p0 = (const float2*)&x[(size_t)r0g * F_IN];
    const float2* p1 = (const float2*)&x[(size_t)r1g * F_IN];
    const float2 z2 = make_float2(0.f, 0.f);

    float acc[8][4];
    #pragma unroll
    for (int j = 0; j < 8; j++)
        #pragma unroll
        for (int q = 0; q < 4; q++)
            acc[j][q] = 0.0f;

    const int afrag = lane >> 3;
    const int arow  = lane & 7;

    float2 c00 = v0 ? p0[tig]     : z2;
    float2 c10 = v1 ? p1[tig]     : z2;
    float2 c01 = v0 ? p0[tig + 4] : z2;
    float2 c11 = v1 ? p1[tig + 4] : z2;

    #pragma unroll
    for (int kk = 0; kk < 8; kk++) {
        float2 n00, n10, n01, n11;
        if (kk < 7) {
            int o = (kk + 1) * 8 + tig;
            n00 = v0 ? p0[o]     : z2;
            n10 = v1 ? p1[o]     : z2;
            n01 = v0 ? p0[o + 4] : z2;
            n11 = v1 ? p1[o + 4] : z2;
        }

        uint32_t ahi[4], alo[4];
        ahi[0] = pack_hi(c00); alo[0] = pack_lo(c00);
        ahi[1] = pack_hi(c10); alo[1] = pack_lo(c10);
        ahi[2] = pack_hi(c01); alo[2] = pack_lo(c01);
        ahi[3] = pack_hi(c11); alo[3] = pack_lo(c11);

        #pragma unroll
        for (int j2 = 0; j2 < 4; j2++) {
            uint32_t b_off = (uint32_t)((j2 * 16 + (afrag >> 1) * 8 + arow) * ASTR
                                        + (kk * 16 + (afrag & 1) * 8) * 2);
            uint32_t bhi[4], blo[4];
            ldmatrix_x4(bhi, sb + SM_BHI + b_off);
            ldmatrix_x4(blo, sb + SM_BLO + b_off);

            mma_bf16(acc[j2 * 2 + 0], ahi, bhi + 0);
            mma_bf16(acc[j2 * 2 + 1], ahi, bhi + 2);
            mma_bf16(acc[j2 * 2 + 0], ahi, blo + 0);
            mma_bf16(acc[j2 * 2 + 1], ahi, blo + 2);
            mma_bf16(acc[j2 * 2 + 0], alo, bhi + 0);
            mma_bf16(acc[j2 * 2 + 1], alo, bhi + 2);
        }

        c00 = n00; c10 = n10; c01 = n01; c11 = n11;
    }

    int r0 = row0 + wid * 16 + (lane >> 2);
    int c0 = (lane & 3) * 2;
    float tv0 = 0.f, tv1 = 0.f;
    if (r0 < N_NODES)     tv0 = __ldg(&t[r0]);
    if (r0 + 8 < N_NODES) tv1 = __ldg(&t[r0 + 8]);

    #pragma unroll
    for (int j = 0; j < 8; j++) {
        if (r0 < N_NODES) {
            float2 v = make_float2(acc[j][0] * tv0, acc[j][1] * tv0);
            *(float2*)&g_support[(size_t)r0 * F_OUT + j * 8 + c0] = v;
        }
        if (r0 + 8 < N_NODES) {
            float2 v = make_float2(acc[j][2] * tv1, acc[j][3] * tv1);
            *(float2*)&g_support[(size_t)(r0 + 8) * F_OUT + j * 8 + c0] = v;
        }
    }

    // ---- tail: bias-init out + zero g_count (runs before kernel 2's hist)
    {
        const int total4 = N_NODES * F_OUT / 4;
        const int stride = gridDim.x * GT;
        float4* out4 = (float4*)out;
        float4 b0 = *(const float4*)&bias[(tid & 15) * 4];
        for (int i = blockIdx.x * GT + tid; i < total4; i += stride)
            out4[i] = b0;
        for (int i = blockIdx.x * GT + tid; i < N_NODES; i += stride)
            g_count[i] = 0;
    }
}

// ===========================================================================
// Kernel 2: fused src-CSR build + register-resident scatter (persistent)
// ===========================================================================
__device__ __forceinline__ void grid_barrier()
{
    __syncthreads();
    if (threadIdx.x == 0) {
        __threadfence();
        int gen = *(volatile int*)&g_bar_gen;
        int arrived = atomicAdd(&g_bar_count, 1);
        if (arrived == FB - 1) {
            g_bar_count = 0;
            __threadfence();
            atomicAdd(&g_bar_gen, 1);
        } else {
            while (*(volatile int*)&g_bar_gen == gen)
                __nanosleep(64);
        }
        __threadfence();
    }
    __syncthreads();
}

__device__ __forceinline__ int block_exscan256(int v)
{
    const int tid = threadIdx.x;
    const int lane = tid & 31;
    const int w = tid >> 5;
    int x = v;
    #pragma unroll
    for (int off = 1; off < 32; off <<= 1) {
        int y = __shfl_up_sync(0xFFFFFFFFu, x, off);
        if (lane >= off) x += y;
    }
    __shared__ int wsum[8];
    if (lane == 31) wsum[w] = x;
    __syncthreads();
    if (w == 0 && lane < 8) {
        int s = wsum[lane];
        #pragma unroll
        for (int off = 1; off < 8; off <<= 1) {
            int y = __shfl_up_sync(0xFFu, s, off);
            if (lane >= off) s += y;
        }
        wsum[lane] = s;
    }
    __syncthreads();
    int woff = (w == 0) ? 0 : wsum[w - 1];
    int r = woff + x - v;
    __syncthreads();
    return r;
}

__device__ __forceinline__ void red_add_v2(float* addr, float a, float b)
{
    asm volatile("red.global.add.v2.f32 [%0], {%1, %2};"
                 :: "l"(addr), "f"(a), "f"(b) : "memory");
}

__global__ void __launch_bounds__(256, 3)
sort_scatter_kernel(const int* __restrict__ src,
                    const int* __restrict__ dst,
                    const float* __restrict__ edge_vals,
                    float* __restrict__ out)
{
    const int tid = threadIdx.x;
    const int bid = blockIdx.x;
    const int gthread = bid * 256 + tid;
    const int nthreads = FB * 256;

    // P1: histogram of src (g_count zeroed by kernel 1)
    for (int q = gthread; q < E_EDGES / 4; q += nthreads) {
        int4 s = __ldg((const int4*)src + q);
        atomicAdd(&g_count[s.x], 1);
        atomicAdd(&g_count[s.y], 1);
        atomicAdd(&g_count[s.z], 1);
        atomicAdd(&g_count[s.w], 1);
    }
    grid_barrier();

    // P2a: per-block partial scans
    if (bid < SCAN_B) {
        int idx = bid * 256 + tid;
        int v = (idx < N_NODES) ? __ldcg(&g_count[idx]) : 0;
        int ex = block_exscan256(v);
        if (tid == 255) g_bsum[bid] = ex + v;
    }
    grid_barrier();

    // P2b: scan the block sums
    if (bid == 0) {
        int v = (tid < SCAN_B) ? __ldcg(&g_bsum[tid]) : 0;
        int ex = block_exscan256(v);
        if (tid < SCAN_B) g_bsum[tid] = ex;
    }
    grid_barrier();

    // P2c: final offsets + cursor copy
    if (bid < SCAN_B) {
        int idx = bid * 256 + tid;
        int v = (idx < N_NODES) ? __ldcg(&g_count[idx]) : 0;
        int ex = block_exscan256(v) + __ldcg(&g_bsum[bid]);
        if (idx < N_NODES) {
            g_start[idx] = ex;
            g_count[idx] = ex;
        }
    }
    if (gthread == 0) g_start[N_NODES] = E_EDGES;
    grid_barrier();

    // P3: reorder edges by src; store (dst, val)
    for (int q = gthread; q < E_EDGES / 4; q += nthreads) {
        int4   s = __ldg((const int4*)src + q);
        int4   d = __ldg((const int4*)dst + q);
        float4 v = __ldg((const float4*)edge_vals + q);
        int p0 = atomicAdd(&g_count[s.x], 1);
        int p1 = atomicAdd(&g_count[s.y], 1);
        int p2 = atomicAdd(&g_count[s.z], 1);
        int p3 = atomicAdd(&g_count[s.w], 1);
        g_edges[p0] = make_int2(d.x, __float_as_int(v.x));
        g_edges[p1] = make_int2(d.y, __float_as_int(v.y));
        g_edges[p2] = make_int2(d.z, __float_as_int(v.z));
        g_edges[p3] = make_int2(d.w, __float_as_int(v.w));
    }
    grid_barrier();

    // P4: scatter — warp per src node; support row lives in registers.
    // Lanes cooperatively load up to 32 edges at once, shfl-broadcast each,
    // fire one red.v2 (256 B atomic wavefront per edge).  REDs don't return,
    // so the only latency chain is the coalesced edge load per 32 edges.
    {
        const int lane = tid & 31;
        const int wrp  = gthread >> 5;
        const int nwrp = nthreads >> 5;

        for (int n = wrp; n < N_NODES; n += nwrp) {
            int beg = __ldcg(&g_start[n]);
            int end = __ldcg(&g_start[n + 1]);
            if (beg == end) continue;

            float2 srow = *((const float2*)&g_support[(size_t)n * F_OUT] + lane);

            int i = beg;
            while (i < end) {
                int cnt = end - i;
                if (cnt > 32) cnt = 32;
                int2 my = make_int2(0, 0);
                if (lane < cnt) my = __ldcg(&g_edges[i + lane]);
                for (int k = 0; k < cnt; k++) {
                    int   dn = __shfl_sync(0xFFFFFFFFu, my.x, k);
                    float ev = __int_as_float(__shfl_sync(0xFFFFFFFFu, my.y, k));
                    red_add_v2(&out[(size_t)dn * F_OUT + lane * 2],
                               srow.x * ev, srow.y * ev);
                }
                i += cnt;
            }
        }
    }
}

// ---------------------------------------------------------------------------
// Launch.  Inputs (metadata order): x, t, src, dst, edge_vals, weight, bias
// ---------------------------------------------------------------------------
extern "C" void kernel_launch(void* const* d_in, const int* in_sizes, int n_in,
                              void* d_out, int out_size)
{
    const float* x         = (const float*)d_in[0];
    const float* t         = (const float*)d_in[1];
    const int*   src       = (const int*)d_in[2];
    const int*   dst       = (const int*)d_in[3];
    const float* edge_vals = (const float*)d_in[4];
    const float* weight    = (const float*)d_in[5];
    const float* bias      = (const float*)d_in[6];
    float*       out       = (float*)d_out;

    cudaFuncSetAttribute(gemm_tc_kernel,
                         cudaFuncAttributeMaxDynamicSharedMemorySize, SM_TOTAL);

    // 1. support = (X @ W) * t ; out = bias ; g_count = 0
    int gemm_blocks = (N_NODES + 127) / 128;            // 391
    gemm_tc_kernel<<<gemm_blocks, GT, SM_TOTAL>>>(x, t, weight, bias, out);

    // 2. src-CSR build + register-resident scatter
    sort_scatter_kernel<<<FB, 256>>>(src, dst, edge_vals, out);
}

// round 17
// speedup vs baseline: 1.0022x; 1.0022x over previous
#include <cuda_runtime.h>
#include <cuda_bf16.h>
#include <cstdint>

#define N_NODES 50000
#define E_EDGES 800000
#define F_IN    128
#define F_OUT   64

// Static scratch (no g_support anymore — support lives in smem only)
__device__ int  g_count[N_NODES];              // hist -> cursor
__device__ int  g_start[N_NODES + 1];          // CSR offsets (by src)
__device__ int  g_bsum[256];                   // block sums for scan
__device__ int2 g_edges[E_EDGES];              // (dst, val bits) sorted by src

// grid barrier state (self-resetting -> replay-deterministic)
__device__ int g_bar_count;
__device__ int g_bar_gen;

#define FB 444
#define SCAN_B 196

// ===========================================================================
// Kernel 1: persistent CSR build (by src) + bias-init of out.
// Phases: P0 zero+bias | P1 hist | P2a/b/c scan | P3 reorder.
// ===========================================================================
__device__ __forceinline__ void grid_barrier()
{
    __syncthreads();
    if (threadIdx.x == 0) {
        __threadfence();
        int gen = *(volatile int*)&g_bar_gen;
        int arrived = atomicAdd(&g_bar_count, 1);
        if (arrived == FB - 1) {
            g_bar_count = 0;
            __threadfence();
            atomicAdd(&g_bar_gen, 1);
        } else {
            while (*(volatile int*)&g_bar_gen == gen)
                __nanosleep(64);
        }
        __threadfence();
    }
    __syncthreads();
}

__device__ __forceinline__ int block_exscan256(int v)
{
    const int tid = threadIdx.x;
    const int lane = tid & 31;
    const int w = tid >> 5;
    int x = v;
    #pragma unroll
    for (int off = 1; off < 32; off <<= 1) {
        int y = __shfl_up_sync(0xFFFFFFFFu, x, off);
        if (lane >= off) x += y;
    }
    __shared__ int wsum[8];
    if (lane == 31) wsum[w] = x;
    __syncthreads();
    if (w == 0 && lane < 8) {
        int s = wsum[lane];
        #pragma unroll
        for (int off = 1; off < 8; off <<= 1) {
            int y = __shfl_up_sync(0xFFu, s, off);
            if (lane >= off) s += y;
        }
        wsum[lane] = s;
    }
    __syncthreads();
    int woff = (w == 0) ? 0 : wsum[w - 1];
    int r = woff + x - v;
    __syncthreads();
    return r;
}

__global__ void __launch_bounds__(256, 3)
build_kernel(const int* __restrict__ src,
             const int* __restrict__ dst,
             const float* __restrict__ edge_vals,
             const float* __restrict__ bias,
             float* __restrict__ out)
{
    const int tid = threadIdx.x;
    const int bid = blockIdx.x;
    const int gthread = bid * 256 + tid;
    const int nthreads = FB * 256;

    // P0: bias-init out + zero g_count
    {
        float4 b0 = *(const float4*)&bias[(tid & 15) * 4];
        float4* out4 = (float4*)out;
        const int total4 = N_NODES * F_OUT / 4;
        for (int i = gthread; i < total4; i += nthreads)
            out4[i] = b0;
        for (int i = gthread; i < N_NODES; i += nthreads)
            g_count[i] = 0;
    }
    grid_barrier();

    // P1: histogram of src
    for (int q = gthread; q < E_EDGES / 4; q += nthreads) {
        int4 s = __ldg((const int4*)src + q);
        atomicAdd(&g_count[s.x], 1);
        atomicAdd(&g_count[s.y], 1);
        atomicAdd(&g_count[s.z], 1);
        atomicAdd(&g_count[s.w], 1);
    }
    grid_barrier();

    // P2a: per-block partial scans
    if (bid < SCAN_B) {
        int idx = bid * 256 + tid;
        int v = (idx < N_NODES) ? __ldcg(&g_count[idx]) : 0;
        int ex = block_exscan256(v);
        if (tid == 255) g_bsum[bid] = ex + v;
    }
    grid_barrier();

    // P2b: scan the block sums
    if (bid == 0) {
        int v = (tid < SCAN_B) ? __ldcg(&g_bsum[tid]) : 0;
        int ex = block_exscan256(v);
        if (tid < SCAN_B) g_bsum[tid] = ex;
    }
    grid_barrier();

    // P2c: final offsets + cursor copy
    if (bid < SCAN_B) {
        int idx = bid * 256 + tid;
        int v = (idx < N_NODES) ? __ldcg(&g_count[idx]) : 0;
        int ex = block_exscan256(v) + __ldcg(&g_bsum[bid]);
        if (idx < N_NODES) {
            g_start[idx] = ex;
            g_count[idx] = ex;
        }
    }
    if (gthread == 0) g_start[N_NODES] = E_EDGES;
    grid_barrier();

    // P3: reorder edges by src; payload = (dst, val)
    for (int q = gthread; q < E_EDGES / 4; q += nthreads) {
        int4   s = __ldg((const int4*)src + q);
        int4   d = __ldg((const int4*)dst + q);
        float4 v = __ldg((const float4*)edge_vals + q);
        int p0 = atomicAdd(&g_count[s.x], 1);
        int p1 = atomicAdd(&g_count[s.y], 1);
        int p2 = atomicAdd(&g_count[s.z], 1);
        int p3 = atomicAdd(&g_count[s.w], 1);
        g_edges[p0] = make_int2(d.x, __float_as_int(v.x));
        g_edges[p1] = make_int2(d.y, __float_as_int(v.y));
        g_edges[p2] = make_int2(d.z, __float_as_int(v.z));
        g_edges[p3] = make_int2(d.w, __float_as_int(v.w));
    }
}

// ===========================================================================
// Kernel 2: fused GEMM + smem-resident scatter.  NO grid barriers.
// CTA: rows row0..row0+127.  GEMM (proven) -> rows to smem (reusing B smem)
// -> warp-per-row scatter via src-CSR, red.v2 atomics into out.
// ===========================================================================
#define GT 256
#define ASTR 272
#define SM_BHI 0
#define SM_BLO (SM_BHI + 64 * ASTR)
#define SM_TOTAL (SM_BLO + 64 * ASTR)          // 34816
#define RSTR 66                                // row stride (floats), bank-spread

__device__ __forceinline__ uint32_t smem_u32(const void* p) {
    uint32_t a;
    asm("{ .reg .u64 tmp; cvta.to.shared.u64 tmp, %1; cvt.u32.u64 %0, tmp; }"
        : "=r"(a) : "l"(p));
    return a;
}

__device__ __forceinline__ void ldmatrix_x4(uint32_t* r, uint32_t addr) {
    asm volatile("ldmatrix.sync.aligned.m8n8.x4.shared.b16 {%0,%1,%2,%3}, [%4];"
                 : "=r"(r[0]), "=r"(r[1]), "=r"(r[2]), "=r"(r[3]) : "r"(addr));
}

__device__ __forceinline__ void mma_bf16(float* d, const uint32_t* a,
                                         const uint32_t* b) {
    asm volatile(
        "mma.sync.aligned.m16n8k16.row.col.f32.bf16.bf16.f32 "
        "{%0,%1,%2,%3}, {%4,%5,%6,%7}, {%8,%9}, {%0,%1,%2,%3};"
        : "+f"(d[0]), "+f"(d[1]), "+f"(d[2]), "+f"(d[3])
        : "r"(a[0]), "r"(a[1]), "r"(a[2]), "r"(a[3]), "r"(b[0]), "r"(b[1]));
}

__device__ __forceinline__ uint32_t pack_hi(float2 v) {
    __nv_bfloat162 h = __floats2bfloat162_rn(v.x, v.y);
    return *(uint32_t*)&h;
}
__device__ __forceinline__ uint32_t pack_lo(float2 v) {
    __nv_bfloat162 h = __floats2bfloat162_rn(v.x, v.y);
    float rx = v.x - __bfloat162float(__low2bfloat16(h));
    float ry = v.y - __bfloat162float(__high2bfloat16(h));
    __nv_bfloat162 l = __floats2bfloat162_rn(rx, ry);
    return *(uint32_t*)&l;
}

__device__ __forceinline__ void red_add_v2(float* addr, float a, float b)
{
    asm volatile("red.global.add.v2.f32 [%0], {%1, %2};"
                 :: "l"(addr), "f"(a), "f"(b) : "memory");
}

__global__ void __launch_bounds__(GT, 3)
gemm_scatter_kernel(const float* __restrict__ x,
                    const float* __restrict__ t,
                    const float* __restrict__ weight,
                    float* __restrict__ out)
{
    extern __shared__ char smem[];
    const uint32_t sb = smem_u32(smem);
    const int tid  = threadIdx.x;
    const int wid  = tid >> 5;
    const int lane = tid & 31;
    const int row0 = blockIdx.x * 128;

    // ---- stage B = W^T hi/lo split
    for (int i = tid; i < F_IN * F_OUT; i += GT) {
        int f = i & 63;
        int k = i >> 6;
        float v = __ldg(&weight[i]);
        __nv_bfloat16 h = __float2bfloat16(v);
        __nv_bfloat16 l = __float2bfloat16(v - __bfloat162float(h));
        *(__nv_bfloat16*)(smem + SM_BHI + f * ASTR + k * 2) = h;
        *(__nv_bfloat16*)(smem + SM_BLO + f * ASTR + k * 2) = l;
    }
    __syncthreads();

    // ---- A: direct gmem float2 loads in mma fragment layout
    const int g   = lane >> 2;
    const int tig = lane & 3;
    const int r0g = row0 + wid * 16 + g;
    const int r1g = r0g + 8;
    const bool v0 = r0g < N_NODES;
    const bool v1 = r1g < N_NODES;
    const float2* p0 = (const float2*)&x[(size_t)r0g * F_IN];
    const float2* p1 = (const float2*)&x[(size_t)r1g * F_IN];
    const float2 z2 = make_float2(0.f, 0.f);

    float acc[8][4];
    #pragma unroll
    for (int j = 0; j < 8; j++)
        #pragma unroll
        for (int q = 0; q < 4; q++)
            acc[j][q] = 0.0f;

    const int afrag = lane >> 3;
    const int arow  = lane & 7;

    float2 c00 = v0 ? p0[tig]     : z2;
    float2 c10 = v1 ? p1[tig]     : z2;
    float2 c01 = v0 ? p0[tig + 4] : z2;
    float2 c11 = v1 ? p1[tig + 4] : z2;

    #pragma unroll
    for (int kk = 0; kk < 8; kk++) {
        float2 n00, n10, n01, n11;
        if (kk < 7) {
            int o = (kk + 1) * 8 + tig;
            n00 = v0 ? p0[o]     : z2;
            n10 = v1 ? p1[o]     : z2;
            n01 = v0 ? p0[o + 4] : z2;
            n11 = v1 ? p1[o + 4] : z2;
        }

        uint32_t ahi[4], alo[4];
        ahi[0] = pack_hi(c00); alo[0] = pack_lo(c00);
        ahi[1] = pack_hi(c10); alo[1] = pack_lo(c10);
        ahi[2] = pack_hi(c01); alo[2] = pack_lo(c01);
        ahi[3] = pack_hi(c11); alo[3] = pack_lo(c11);

        #pragma unroll
        for (int j2 = 0; j2 < 4; j2++) {
            uint32_t b_off = (uint32_t)((j2 * 16 + (afrag >> 1) * 8 + arow) * ASTR
                                        + (kk * 16 + (afrag & 1) * 8) * 2);
            uint32_t bhi[4], blo[4];
            ldmatrix_x4(bhi, sb + SM_BHI + b_off);
            ldmatrix_x4(blo, sb + SM_BLO + b_off);

            mma_bf16(acc[j2 * 2 + 0], ahi, bhi + 0);
            mma_bf16(acc[j2 * 2 + 1], ahi, bhi + 2);
            mma_bf16(acc[j2 * 2 + 0], ahi, blo + 0);
            mma_bf16(acc[j2 * 2 + 1], ahi, blo + 2);
            mma_bf16(acc[j2 * 2 + 0], alo, bhi + 0);
            mma_bf16(acc[j2 * 2 + 1], alo, bhi + 2);
        }

        c00 = n00; c10 = n10; c01 = n01; c11 = n11;
    }

    // ---- all warps done reading B; reuse smem as the row buffer
    __syncthreads();
    float* rows = (float*)smem;          // 128 rows x RSTR floats = 33792 B

    {
        int lr = wid * 16 + (lane >> 2);
        int c0 = (lane & 3) * 2;
        float tv0 = (row0 + lr     < N_NODES) ? __ldg(&t[row0 + lr])     : 0.f;
        float tv1 = (row0 + lr + 8 < N_NODES) ? __ldg(&t[row0 + lr + 8]) : 0.f;
        #pragma unroll
        for (int j = 0; j < 8; j++) {
            rows[lr * RSTR + j * 8 + c0]           = acc[j][0] * tv0;
            rows[lr * RSTR + j * 8 + c0 + 1]       = acc[j][1] * tv0;
            rows[(lr + 8) * RSTR + j * 8 + c0]     = acc[j][2] * tv1;
            rows[(lr + 8) * RSTR + j * 8 + c0 + 1] = acc[j][3] * tv1;
        }
    }
    __syncthreads();

    // ---- scatter: warp per row (stride 8), lane owns a float2 of the row
    for (int rl = wid; rl < 128; rl += 8) {
        int n = row0 + rl;
        if (n >= N_NODES) break;
        int beg = __ldg(&g_start[n]);
        int end = __ldg(&g_start[n + 1]);
        if (beg == end) continue;

        float2 srow = make_float2(rows[rl * RSTR + lane * 2],
                                  rows[rl * RSTR + lane * 2 + 1]);

        int i = beg;
        while (i < end) {
            int cnt = end - i;
            if (cnt > 32) cnt = 32;
            int2 my = make_int2(0, 0);
            if (lane < cnt) my = __ldg(&g_edges[i + lane]);
            for (int k = 0; k < cnt; k++) {
                int   dn = __shfl_sync(0xFFFFFFFFu, my.x, k);
                float ev = __int_as_float(__shfl_sync(0xFFFFFFFFu, my.y, k));
                red_add_v2(&out[(size_t)dn * F_OUT + lane * 2],
                           srow.x * ev, srow.y * ev);
            }
            i += cnt;
        }
    }
}

// ---------------------------------------------------------------------------
// Launch.  Inputs (metadata order): x, t, src, dst, edge_vals, weight, bias
// ---------------------------------------------------------------------------
extern "C" void kernel_launch(void* const* d_in, const int* in_sizes, int n_in,
                              void* d_out, int out_size)
{
    const float* x         = (const float*)d_in[0];
    const float* t         = (const float*)d_in[1];
    const int*   src       = (const int*)d_in[2];
    const int*   dst       = (const int*)d_in[3];
    const float* edge_vals = (const float*)d_in[4];
    const float* weight    = (const float*)d_in[5];
    const float* bias      = (const float*)d_in[6];
    float*       out       = (float*)d_out;

    cudaFuncSetAttribute(gemm_scatter_kernel,
                         cudaFuncAttributeMaxDynamicSharedMemorySize, SM_TOTAL);

    // 1. src-CSR build + bias-init (persistent, 5 internal barriers)
    build_kernel<<<FB, 256>>>(src, dst, edge_vals, bias, out);

    // 2. fused GEMM + smem-resident scatter (no internal barriers)
    int blocks = (N_NODES + 127) / 128;                 // 391
    gemm_scatter_kernel<<<blocks, GT, SM_TOTAL>>>(x, t, weight, out);
}